// round 13
// baseline (speedup 1.0000x reference)
#include <cuda_runtime.h>
#include <cuda_fp16.h>
#include <cstdint>

#define HID      512
#define NOBJ     8192
#define NREL     32768
#define POOL     4096
#define NRELCLS  51
#define NOBJCLS  151

// -------------------- device scratch --------------------
__device__ __align__(256) __half g_edge_hi[NOBJ * 1024];
__device__ __align__(256) __half g_wcatT[POOL * 1024];   // [n][k] fp16
__device__ __align__(256) __half g_wctxT[64 * POOL];     // [cls pad64][k] fp16
__device__ __align__(256) __half g_ec_hi[NOBJ * HID];    // edge_ctx fp16
__device__ __align__(256) __half g_wembT[1024 * HID];    // [n][k] fp16
__device__ __align__(256) __half g_U[NOBJ * POOL];       // head_rep @ Wcat_top
__device__ __align__(256) __half g_V[NOBJ * POOL];       // tail_rep @ Wcat_bot + bcat

// -------------------- helpers --------------------
__device__ __forceinline__ uint32_t smem_u32(const void* p) {
    uint32_t a;
    asm("{ .reg .u64 t; cvta.to.shared.u64 t, %1; cvt.u32.u64 %0, t; }" : "=r"(a) : "l"(p));
    return a;
}
#define CP16(d, s)   asm volatile("cp.async.cg.shared.global [%0], [%1], 16;" :: "r"(d), "l"(s) : "memory")
#define CP_COMMIT()  asm volatile("cp.async.commit_group;" ::: "memory")
#define WAITG(n)     asm volatile("cp.async.wait_group %0;" :: "n"(n) : "memory")

__device__ __forceinline__ void ldsm4(uint32_t* r, uint32_t a) {
    asm volatile("ldmatrix.sync.aligned.m8n8.x4.shared.b16 {%0,%1,%2,%3}, [%4];"
                 : "=r"(r[0]), "=r"(r[1]), "=r"(r[2]), "=r"(r[3]) : "r"(a));
}
__device__ __forceinline__ void mma16816(float* d, const uint32_t* a, uint32_t b0, uint32_t b1) {
    asm volatile(
        "mma.sync.aligned.m16n8k16.row.col.f32.f16.f16.f32 "
        "{%0,%1,%2,%3}, {%4,%5,%6,%7}, {%8,%9}, {%0,%1,%2,%3};"
        : "+f"(d[0]), "+f"(d[1]), "+f"(d[2]), "+f"(d[3])
        : "r"(a[0]), "r"(a[1]), "r"(a[2]), "r"(a[3]), "r"(b0), "r"(b1));
}
__device__ __forceinline__ uint32_t packh(float e0, float e1) {
    uint32_t r;
    asm("cvt.rn.f16x2.f32 %0, %1, %2;" : "=r"(r) : "f"(e1), "f"(e0));  // low = e0
    return r;
}

// -------------------- smem layouts --------------------
#define UVSTAGE  98304           // A [128m][128k] 32KB + B [256n][128k] 64KB
#define UV_A     0
#define UV_B     32768
#define SMEM_UV  196608

#define ZP_Z     0               // 2 bufs x 2 subs x 16KB = 64KB
#define ZP_WC    65536           // 2 bufs x 2 subs x 8KB  = 32KB
#define ZP_P0    98304
#define ZP_P1    98816
#define ZP_OP    99328
#define SMEM_ZP  99840           // 97.5KB -> 2 CTAs/SM

// ===========================================================================
// Preps
// ===========================================================================
__global__ void k_ec_prep(const float* __restrict__ src) {
    int idx = blockIdx.x * 256 + threadIdx.x;
    g_ec_hi[idx] = __float2half_rn(src[idx]);
}

__global__ void k_wemb_prep(const float* __restrict__ src) {  // [512][1024] -> [1024][512]
    __shared__ float tile[32][33];
    int tx = threadIdx.x, ty = threadIdx.y;
    int c0 = blockIdx.x * 32, r0 = blockIdx.y * 32;
    for (int i = ty; i < 32; i += 8)
        tile[i][tx] = src[(size_t)(r0 + i) * 1024 + c0 + tx];
    __syncthreads();
    for (int i = ty; i < 32; i += 8)
        g_wembT[(size_t)(c0 + i) * HID + r0 + tx] = __float2half_rn(tile[tx][i]);
}

__global__ void k_wcat_prep(const float* __restrict__ src) {  // [1024][4096] -> [4096][1024]
    __shared__ float tile[32][33];
    int tx = threadIdx.x, ty = threadIdx.y;
    int c0 = blockIdx.x * 32, r0 = blockIdx.y * 32;
    for (int i = ty; i < 32; i += 8)
        tile[i][tx] = src[(size_t)(r0 + i) * POOL + c0 + tx];
    __syncthreads();
    for (int i = ty; i < 32; i += 8)
        g_wcatT[(size_t)(c0 + i) * 1024 + r0 + tx] = __float2half_rn(tile[tx][i]);
}

__global__ void k_wctx_prep(const float* __restrict__ Wctx) {
    int idx = blockIdx.x * 256 + threadIdx.x;   // 64*4096
    int c = idx >> 12, k = idx & 4095;
    float v = (c < NRELCLS) ? Wctx[(size_t)k * NRELCLS + c] : 0.f;
    g_wctxT[idx] = __float2half_rn(v);
}

// ===========================================================================
// GEMM1 (mma, UV shape): edge_rep = relu(edge_ctx @ W_post_emb + b) -> fp16
// ===========================================================================
__global__ __launch_bounds__(256, 1) void k_gemm1_mma(const float* __restrict__ bias)
{
    extern __shared__ __align__(1024) char smc[];
    const uint32_t sb = smem_u32(smc);
    const int t = threadIdx.x;
    const int lane = t & 31, wid = t >> 5;
    const int wm = wid >> 2, wn = wid & 3;
    const int m0 = blockIdx.x * 128, n0 = blockIdx.y * 256;

    auto load_stage = [&](int kc) {      // kc in units of 128k
        const uint32_t base = sb + (kc & 1) * UVSTAGE;
#pragma unroll
        for (int i = 0; i < 8; i++) {
            int idx = t + i * 256;
            int row = idx >> 4, j = idx & 15;
            uint32_t d = (uint32_t)row * 256 + (((uint32_t)j * 16) ^ ((uint32_t)(row & 7) << 4));
            CP16(base + UV_A + d, &g_ec_hi[(size_t)(m0 + row) * HID + kc * 128 + j * 8]);
        }
#pragma unroll
        for (int i = 0; i < 16; i++) {
            int idx = t + i * 256;
            int row = idx >> 4, j = idx & 15;
            uint32_t d = (uint32_t)row * 256 + (((uint32_t)j * 16) ^ ((uint32_t)(row & 7) << 4));
            CP16(base + UV_B + d, &g_wembT[(size_t)(n0 + row) * HID + kc * 128 + j * 8]);
        }
    };
    load_stage(0); CP_COMMIT();
    load_stage(1); CP_COMMIT();

    const uint32_t xorv = (lane & 7) << 4;
    const uint32_t khb  = (lane >> 4) * 16;
    const uint32_t arow = (uint32_t)(wm * 64 + (lane & 15)) * 256;
    const uint32_t brow = (uint32_t)(wn * 64 + (lane & 15)) * 256;

    float acc[4][8][4];
#pragma unroll
    for (int a = 0; a < 4; a++)
#pragma unroll
        for (int b = 0; b < 8; b++)
#pragma unroll
            for (int c = 0; c < 4; c++) acc[a][b][c] = 0.f;

    for (int kc = 0; kc < 4; kc++) {
        if (kc == 3) { WAITG(0); } else { WAITG(1); }
        __syncthreads();
        const uint32_t base = sb + (kc & 1) * UVSTAGE;
#pragma unroll
        for (int ks = 0; ks < 8; ks++) {
            const uint32_t col = (uint32_t)(ks * 32 + khb) ^ xorv;
            uint32_t bf[4][4];
#pragma unroll
            for (int q = 0; q < 4; q++)
                ldsm4(bf[q], base + UV_B + brow + q * 16 * 256 + col);
            uint32_t ah[4][4];
#pragma unroll
            for (int mt = 0; mt < 4; mt++)
                ldsm4(ah[mt], base + UV_A + arow + mt * 16 * 256 + col);
#pragma unroll
            for (int mt = 0; mt < 4; mt++)
#pragma unroll
                for (int nt = 0; nt < 8; nt++)
                    mma16816(acc[mt][nt], ah[mt],
                             bf[nt >> 1][nt & 1], bf[nt >> 1][2 + (nt & 1)]);
        }
        __syncthreads();
        if (kc + 2 < 4) { load_stage(kc + 2); CP_COMMIT(); }
    }

#pragma unroll
    for (int mt = 0; mt < 4; mt++) {
        const int mloc = wm * 64 + mt * 16 + (lane >> 2);
#pragma unroll
        for (int nt = 0; nt < 8; nt++) {
            const int nl = n0 + wn * 64 + nt * 8 + (lane & 3) * 2;
            float2 bb = *(const float2*)&bias[nl];
            *(uint32_t*)&g_edge_hi[(size_t)(m0 + mloc) * 1024 + nl] =
                packh(fmaxf(acc[mt][nt][0] + bb.x, 0.f), fmaxf(acc[mt][nt][1] + bb.y, 0.f));
            *(uint32_t*)&g_edge_hi[(size_t)(m0 + mloc + 8) * 1024 + nl] =
                packh(fmaxf(acc[mt][nt][2] + bb.x, 0.f), fmaxf(acc[mt][nt][3] + bb.y, 0.f));
        }
    }
}

// ===========================================================================
// UV GEMM: U = head_rep @ Wcat_top, V = tail_rep @ Wcat_bot (+bcat folded)
// blockIdx.z selects half. 256 threads, M128 x N256, warp 64x64, 4 k-stages.
// ===========================================================================
__global__ __launch_bounds__(256, 1) void k_uv(const float* __restrict__ bcat)
{
    extern __shared__ __align__(1024) char smc[];
    const uint32_t sb = smem_u32(smc);
    const int t = threadIdx.x;
    const int lane = t & 31, wid = t >> 5;
    const int wm = wid >> 2, wn = wid & 3;
    const int m0 = blockIdx.x * 128, n0 = blockIdx.y * 256;
    const int zsel = blockIdx.z;
    const int koff = zsel * 512;
    __half* dst = zsel ? g_V : g_U;

    auto load_stage = [&](int kc) {
        const uint32_t base = sb + (kc & 1) * UVSTAGE;
#pragma unroll
        for (int i = 0; i < 8; i++) {
            int idx = t + i * 256;
            int row = idx >> 4, j = idx & 15;
            uint32_t d = (uint32_t)row * 256 + (((uint32_t)j * 16) ^ ((uint32_t)(row & 7) << 4));
            CP16(base + UV_A + d, &g_edge_hi[(size_t)(m0 + row) * 1024 + koff + kc * 128 + j * 8]);
        }
#pragma unroll
        for (int i = 0; i < 16; i++) {
            int idx = t + i * 256;
            int row = idx >> 4, j = idx & 15;
            uint32_t d = (uint32_t)row * 256 + (((uint32_t)j * 16) ^ ((uint32_t)(row & 7) << 4));
            CP16(base + UV_B + d, &g_wcatT[(size_t)(n0 + row) * 1024 + koff + kc * 128 + j * 8]);
        }
    };
    load_stage(0); CP_COMMIT();
    load_stage(1); CP_COMMIT();

    const uint32_t xorv = (lane & 7) << 4;
    const uint32_t khb  = (lane >> 4) * 16;
    const uint32_t arow = (uint32_t)(wm * 64 + (lane & 15)) * 256;
    const uint32_t brow = (uint32_t)(wn * 64 + (lane & 15)) * 256;

    float acc[4][8][4];
#pragma unroll
    for (int a = 0; a < 4; a++)
#pragma unroll
        for (int b = 0; b < 8; b++)
#pragma unroll
            for (int c = 0; c < 4; c++) acc[a][b][c] = 0.f;

    for (int kc = 0; kc < 4; kc++) {
        if (kc == 3) { WAITG(0); } else { WAITG(1); }
        __syncthreads();
        const uint32_t base = sb + (kc & 1) * UVSTAGE;
#pragma unroll
        for (int ks = 0; ks < 8; ks++) {
            const uint32_t col = (uint32_t)(ks * 32 + khb) ^ xorv;
            uint32_t bf[4][4];
#pragma unroll
            for (int q = 0; q < 4; q++)
                ldsm4(bf[q], base + UV_B + brow + q * 16 * 256 + col);
            uint32_t ah[4][4];
#pragma unroll
            for (int mt = 0; mt < 4; mt++)
                ldsm4(ah[mt], base + UV_A + arow + mt * 16 * 256 + col);
#pragma unroll
            for (int mt = 0; mt < 4; mt++)
#pragma unroll
                for (int nt = 0; nt < 8; nt++)
                    mma16816(acc[mt][nt], ah[mt],
                             bf[nt >> 1][nt & 1], bf[nt >> 1][2 + (nt & 1)]);
        }
        __syncthreads();
        if (kc + 2 < 4) { load_stage(kc + 2); CP_COMMIT(); }
    }

    const float zf = zsel ? 1.f : 0.f;   // fold bcat into V only
#pragma unroll
    for (int mt = 0; mt < 4; mt++) {
        const int mloc = wm * 64 + mt * 16 + (lane >> 2);
#pragma unroll
        for (int nt = 0; nt < 8; nt++) {
            const int nl = wn * 64 + nt * 8 + (lane & 3) * 2;
            float2 bb = *(const float2*)&bcat[n0 + nl];
            float bx = bb.x * zf, by = bb.y * zf;
            *(uint32_t*)&dst[(size_t)(m0 + mloc) * POOL + n0 + nl] =
                packh(acc[mt][nt][0] + bx, acc[mt][nt][1] + by);
            *(uint32_t*)&dst[(size_t)(m0 + mloc + 8) * POOL + n0 + nl] =
                packh(acc[mt][nt][2] + bx, acc[mt][nt][3] + by);
        }
    }
}

// ===========================================================================
// z-pass: z = (U[p0] + V'[p1]) * union -> fp16 smem -> GEMM3 -> +freq
// 256 threads, 2 CTAs/SM. 32 chunks of 128 pool cols. Double-buffered z+WC,
// ONE __syncthreads per chunk, WC prefetched 1 chunk ahead.
// ===========================================================================
__global__ __launch_bounds__(256, 2) void k_zpass(
    const float* __restrict__ unionf,
    const int*   __restrict__ pairs,
    const int*   __restrict__ obj_preds,
    const float* __restrict__ bctx,
    const float* __restrict__ freq,
    float*       __restrict__ out)
{
    extern __shared__ __align__(1024) char smc[];
    const uint32_t sb = smem_u32(smc);
    const int t = threadIdx.x;
    const int lane = t & 31, wid = t >> 5;
    const int gm = wid >> 1, gn = wid & 1;
    const int r0 = blockIdx.x * 128;

    int* p0s = (int*)(smc + ZP_P0);
    int* p1s = (int*)(smc + ZP_P1);
    int* opx = (int*)(smc + ZP_OP);

    if (t < 128) {
        int a = pairs[(size_t)(r0 + t) * 2 + 0];
        int b = pairs[(size_t)(r0 + t) * 2 + 1];
        p0s[t] = a; p1s[t] = b;
        opx[t] = obj_preds[a] * NOBJCLS + obj_preds[b];
    }
    __syncthreads();

    const int m = t >> 1;
    const int coff = (t & 1) * 64;
    const int sub = t & 1;
    const uint32_t xorm = (uint32_t)(m & 7) << 4;
    const __half* Ubase = &g_U[(size_t)p0s[m] * POOL];
    const __half* Vbase = &g_V[(size_t)p1s[m] * POOL];
    const float*  ubase = &unionf[(size_t)(r0 + m) * POOL];

    const uint32_t xorv = (lane & 7) << 4;
    const uint32_t khb  = (lane >> 4) * 16;
    const uint32_t zrow = (uint32_t)(gm * 32 + (lane & 15)) * 128;
    const uint32_t wrow = (uint32_t)(gn * 32 + (lane & 15)) * 128;

    // WC loader: chunk nc -> buffer (nc & 1)
    auto load_wc = [&](int nc) {
        const int n0 = nc * 128;
        const uint32_t wb = ZP_WC + (uint32_t)(nc & 1) * 16384;
#pragma unroll
        for (int i = 0; i < 4; i++) {
            int idx = t + i * 256;
            int s = idx >> 9, rem = idx & 511, row = rem >> 3, j = rem & 7;
            uint32_t d = wb + (uint32_t)s * 8192 + (uint32_t)row * 128 +
                         (((uint32_t)j * 16) ^ ((uint32_t)(row & 7) << 4));
            CP16(sb + d, &g_wctxT[(size_t)row * POOL + n0 + s * 64 + j * 8]);
        }
    };

    float acc3[2][4][4];
#pragma unroll
    for (int a = 0; a < 2; a++)
#pragma unroll
        for (int b = 0; b < 4; b++)
#pragma unroll
            for (int c = 0; c < 4; c++) acc3[a][b][c] = 0.f;

    load_wc(0); CP_COMMIT();

    for (int nc = 0; nc < 32; nc++) {
        const int n0 = nc * 128;
        const uint32_t zb = ZP_Z + (uint32_t)(nc & 1) * 32768;
        const uint32_t wb = ZP_WC + (uint32_t)(nc & 1) * 16384;

        // elementwise: 64 cols per thread -> z[buf]
        {
            const uint4*  Up = (const uint4*)(Ubase + n0 + coff);
            const uint4*  Vp = (const uint4*)(Vbase + n0 + coff);
            const float4* up = (const float4*)(ubase + n0 + coff);
#pragma unroll
            for (int j = 0; j < 8; j++) {
                uint4 Uv = Up[j], Vv = Vp[j];
                float4 u0 = up[2 * j], u1 = up[2 * j + 1];
                const __half2* pu = (const __half2*)&Uv;
                const __half2* pv = (const __half2*)&Vv;
                float2 f0 = __half22float2(pu[0]), g0 = __half22float2(pv[0]);
                float2 f1 = __half22float2(pu[1]), g1 = __half22float2(pv[1]);
                float2 f2 = __half22float2(pu[2]), g2 = __half22float2(pv[2]);
                float2 f3 = __half22float2(pu[3]), g3 = __half22float2(pv[3]);
                uint4 o;
                o.x = packh((f0.x + g0.x) * u0.x, (f0.y + g0.y) * u0.y);
                o.y = packh((f1.x + g1.x) * u0.z, (f1.y + g1.y) * u0.w);
                o.z = packh((f2.x + g2.x) * u1.x, (f2.y + g2.y) * u1.y);
                o.w = packh((f3.x + g3.x) * u1.z, (f3.y + g3.y) * u1.w);
                *(uint4*)(smc + zb + sub * 16384 + (uint32_t)m * 128 +
                          (((uint32_t)j * 16) ^ xorm)) = o;
            }
        }
        __syncthreads();   // z[buf] ready; all warps past GEMM3(nc-1)

        if (nc + 1 < 32) { load_wc(nc + 1); CP_COMMIT(); WAITG(1); }
        else             { WAITG(0); }

        // GEMM3: acc3 += z[128][128k] x Wctx[64cls][128k]
#pragma unroll
        for (int s = 0; s < 2; s++) {
#pragma unroll
            for (int ks = 0; ks < 4; ks++) {
                const uint32_t col = (uint32_t)(ks * 32 + khb) ^ xorv;
                uint32_t bf[2][4];
                ldsm4(bf[0], sb + wb + s * 8192 + wrow + col);
                ldsm4(bf[1], sb + wb + s * 8192 + wrow + 16 * 128 + col);
                uint32_t zfr[2][4];
#pragma unroll
                for (int mt = 0; mt < 2; mt++)
                    ldsm4(zfr[mt], sb + zb + s * 16384 + zrow + mt * 16 * 128 + col);
#pragma unroll
                for (int mt = 0; mt < 2; mt++)
#pragma unroll
                    for (int nt = 0; nt < 4; nt++)
                        mma16816(acc3[mt][nt], zfr[mt],
                                 bf[nt >> 1][nt & 1], bf[nt >> 1][2 + (nt & 1)]);
            }
        }
    }

    // ---------------- final: out = acc3 + bctx + freq ----------------
#pragma unroll
    for (int mt = 0; mt < 2; mt++) {
        const int m0l = gm * 32 + mt * 16 + (lane >> 2);
#pragma unroll
        for (int r = 0; r < 2; r++) {
            const int mm = m0l + r * 8;
            const int pidx = opx[mm];
            const float* fr = &freq[(size_t)pidx * NRELCLS];
            float* op = &out[(size_t)(r0 + mm) * NRELCLS];
#pragma unroll
            for (int nt = 0; nt < 4; nt++) {
                const int c = gn * 32 + nt * 8 + (lane & 3) * 2;
                if (c < NRELCLS)
                    op[c] = acc3[mt][nt][r * 2 + 0] + bctx[c] + fr[c];
                if (c + 1 < NRELCLS)
                    op[c + 1] = acc3[mt][nt][r * 2 + 1] + bctx[c + 1] + fr[c + 1];
            }
        }
    }
}

// ===========================================================================
extern "C" void kernel_launch(void* const* d_in, const int* in_sizes, int n_in,
                              void* d_out, int out_size)
{
    const float* edge_ctx   = (const float*)d_in[0];
    const float* unionf     = (const float*)d_in[1];
    const int*   pairs      = (const int*)  d_in[2];
    const int*   obj_preds  = (const int*)  d_in[3];
    const float* W_post_emb = (const float*)d_in[4];
    const float* b_post_emb = (const float*)d_in[5];
    const float* W_post_cat = (const float*)d_in[6];
    const float* b_post_cat = (const float*)d_in[7];
    const float* W_ctx      = (const float*)d_in[8];
    const float* b_ctx      = (const float*)d_in[9];
    const float* freq       = (const float*)d_in[10];
    float* out = (float*)d_out;

    cudaFuncSetAttribute(k_gemm1_mma, cudaFuncAttributeMaxDynamicSharedMemorySize, SMEM_UV);
    cudaFuncSetAttribute(k_uv,        cudaFuncAttributeMaxDynamicSharedMemorySize, SMEM_UV);
    cudaFuncSetAttribute(k_zpass,     cudaFuncAttributeMaxDynamicSharedMemorySize, SMEM_ZP);

    k_ec_prep<<<(NOBJ * HID) / 256, 256>>>(edge_ctx);
    k_wemb_prep<<<dim3(1024 / 32, HID / 32), dim3(32, 8)>>>(W_post_emb);
    k_wcat_prep<<<dim3(POOL / 32, 1024 / 32), dim3(32, 8)>>>(W_post_cat);
    k_wctx_prep<<<(64 * POOL) / 256, 256>>>(W_ctx);
    k_gemm1_mma<<<dim3(NOBJ / 128, 1024 / 256), 256, SMEM_UV>>>(b_post_emb);
    k_uv<<<dim3(NOBJ / 128, POOL / 256, 2), 256, SMEM_UV>>>(b_post_cat);
    k_zpass<<<NREL / 128, 256, SMEM_ZP>>>(unionf, pairs, obj_preds,
                                          b_ctx, freq, out);
}

// round 14
// speedup vs baseline: 1.3356x; 1.3356x over previous
#include <cuda_runtime.h>
#include <cuda_fp16.h>
#include <cstdint>

#define HID      512
#define NOBJ     8192
#define NREL     32768
#define POOL     4096
#define NRELCLS  51
#define NOBJCLS  151

// -------------------- device scratch --------------------
__device__ __align__(256) __half g_edge_hi[NOBJ * 1024];
__device__ __align__(256) __half g_wcatT[POOL * 1024];   // [n][k] fp16
__device__ __align__(256) __half g_wctxT[64 * POOL];     // [cls pad64][k] fp16
__device__ __align__(256) __half g_ec_hi[NOBJ * HID];    // edge_ctx fp16
__device__ __align__(256) __half g_wembT[1024 * HID];    // [n][k] fp16
__device__ __align__(256) __half g_U[NOBJ * POOL];       // head_rep @ Wcat_top
__device__ __align__(256) __half g_V[NOBJ * POOL];       // tail_rep @ Wcat_bot + bcat

// -------------------- helpers --------------------
__device__ __forceinline__ uint32_t smem_u32(const void* p) {
    uint32_t a;
    asm("{ .reg .u64 t; cvta.to.shared.u64 t, %1; cvt.u32.u64 %0, t; }" : "=r"(a) : "l"(p));
    return a;
}
#define CP16(d, s)   asm volatile("cp.async.cg.shared.global [%0], [%1], 16;" :: "r"(d), "l"(s) : "memory")
#define CP_COMMIT()  asm volatile("cp.async.commit_group;" ::: "memory")
#define WAITG(n)     asm volatile("cp.async.wait_group %0;" :: "n"(n) : "memory")

__device__ __forceinline__ void ldsm4(uint32_t* r, uint32_t a) {
    asm volatile("ldmatrix.sync.aligned.m8n8.x4.shared.b16 {%0,%1,%2,%3}, [%4];"
                 : "=r"(r[0]), "=r"(r[1]), "=r"(r[2]), "=r"(r[3]) : "r"(a));
}
__device__ __forceinline__ void mma16816(float* d, const uint32_t* a, uint32_t b0, uint32_t b1) {
    asm volatile(
        "mma.sync.aligned.m16n8k16.row.col.f32.f16.f16.f32 "
        "{%0,%1,%2,%3}, {%4,%5,%6,%7}, {%8,%9}, {%0,%1,%2,%3};"
        : "+f"(d[0]), "+f"(d[1]), "+f"(d[2]), "+f"(d[3])
        : "r"(a[0]), "r"(a[1]), "r"(a[2]), "r"(a[3]), "r"(b0), "r"(b1));
}
__device__ __forceinline__ uint32_t packh(float e0, float e1) {
    uint32_t r;
    asm("cvt.rn.f16x2.f32 %0, %1, %2;" : "=r"(r) : "f"(e1), "f"(e0));  // low = e0
    return r;
}

// -------------------- smem layouts --------------------
#define UVSTAGE  98304           // A [128m][128k] 32KB + B [256n][128k] 64KB
#define UV_A     0
#define UV_B     32768
#define SMEM_UV  196608

#define ZP_Z     0               // 2 subs of z [128m][64k] fp16 = 32KB
#define ZP_WC    32768           // 2 subs of Wctx [64cls][64k] = 16KB
#define ZP_P0    49152
#define ZP_P1    49664
#define ZP_OP    50176
#define SMEM_ZP  50688

// ===========================================================================
// Preps
// ===========================================================================
__global__ void k_ec_prep(const float* __restrict__ src) {
    int idx = blockIdx.x * 256 + threadIdx.x;
    g_ec_hi[idx] = __float2half_rn(src[idx]);
}

__global__ void k_wemb_prep(const float* __restrict__ src) {  // [512][1024] -> [1024][512]
    __shared__ float tile[32][33];
    int tx = threadIdx.x, ty = threadIdx.y;
    int c0 = blockIdx.x * 32, r0 = blockIdx.y * 32;
    for (int i = ty; i < 32; i += 8)
        tile[i][tx] = src[(size_t)(r0 + i) * 1024 + c0 + tx];
    __syncthreads();
    for (int i = ty; i < 32; i += 8)
        g_wembT[(size_t)(c0 + i) * HID + r0 + tx] = __float2half_rn(tile[tx][i]);
}

__global__ void k_wcat_prep(const float* __restrict__ src) {  // [1024][4096] -> [4096][1024]
    __shared__ float tile[32][33];
    int tx = threadIdx.x, ty = threadIdx.y;
    int c0 = blockIdx.x * 32, r0 = blockIdx.y * 32;
    for (int i = ty; i < 32; i += 8)
        tile[i][tx] = src[(size_t)(r0 + i) * POOL + c0 + tx];
    __syncthreads();
    for (int i = ty; i < 32; i += 8)
        g_wcatT[(size_t)(c0 + i) * 1024 + r0 + tx] = __float2half_rn(tile[tx][i]);
}

__global__ void k_wctx_prep(const float* __restrict__ Wctx) {
    int idx = blockIdx.x * 256 + threadIdx.x;   // 64*4096
    int c = idx >> 12, k = idx & 4095;
    float v = (c < NRELCLS) ? Wctx[(size_t)k * NRELCLS + c] : 0.f;
    g_wctxT[idx] = __float2half_rn(v);
}

// ===========================================================================
// GEMM1 (mma, UV shape): edge_rep = relu(edge_ctx @ W_post_emb + b) -> fp16
// ===========================================================================
__global__ __launch_bounds__(256, 1) void k_gemm1_mma(const float* __restrict__ bias)
{
    extern __shared__ __align__(1024) char smc[];
    const uint32_t sb = smem_u32(smc);
    const int t = threadIdx.x;
    const int lane = t & 31, wid = t >> 5;
    const int wm = wid >> 2, wn = wid & 3;
    const int m0 = blockIdx.x * 128, n0 = blockIdx.y * 256;

    auto load_stage = [&](int kc) {      // kc in units of 128k
        const uint32_t base = sb + (kc & 1) * UVSTAGE;
#pragma unroll
        for (int i = 0; i < 8; i++) {
            int idx = t + i * 256;
            int row = idx >> 4, j = idx & 15;
            uint32_t d = (uint32_t)row * 256 + (((uint32_t)j * 16) ^ ((uint32_t)(row & 7) << 4));
            CP16(base + UV_A + d, &g_ec_hi[(size_t)(m0 + row) * HID + kc * 128 + j * 8]);
        }
#pragma unroll
        for (int i = 0; i < 16; i++) {
            int idx = t + i * 256;
            int row = idx >> 4, j = idx & 15;
            uint32_t d = (uint32_t)row * 256 + (((uint32_t)j * 16) ^ ((uint32_t)(row & 7) << 4));
            CP16(base + UV_B + d, &g_wembT[(size_t)(n0 + row) * HID + kc * 128 + j * 8]);
        }
    };
    load_stage(0); CP_COMMIT();
    load_stage(1); CP_COMMIT();

    const uint32_t xorv = (lane & 7) << 4;
    const uint32_t khb  = (lane >> 4) * 16;
    const uint32_t arow = (uint32_t)(wm * 64 + (lane & 15)) * 256;
    const uint32_t brow = (uint32_t)(wn * 64 + (lane & 15)) * 256;

    float acc[4][8][4];
#pragma unroll
    for (int a = 0; a < 4; a++)
#pragma unroll
        for (int b = 0; b < 8; b++)
#pragma unroll
            for (int c = 0; c < 4; c++) acc[a][b][c] = 0.f;

    for (int kc = 0; kc < 4; kc++) {
        if (kc == 3) { WAITG(0); } else { WAITG(1); }
        __syncthreads();
        const uint32_t base = sb + (kc & 1) * UVSTAGE;
#pragma unroll
        for (int ks = 0; ks < 8; ks++) {
            const uint32_t col = (uint32_t)(ks * 32 + khb) ^ xorv;
            uint32_t bf[4][4];
#pragma unroll
            for (int q = 0; q < 4; q++)
                ldsm4(bf[q], base + UV_B + brow + q * 16 * 256 + col);
            uint32_t ah[4][4];
#pragma unroll
            for (int mt = 0; mt < 4; mt++)
                ldsm4(ah[mt], base + UV_A + arow + mt * 16 * 256 + col);
#pragma unroll
            for (int mt = 0; mt < 4; mt++)
#pragma unroll
                for (int nt = 0; nt < 8; nt++)
                    mma16816(acc[mt][nt], ah[mt],
                             bf[nt >> 1][nt & 1], bf[nt >> 1][2 + (nt & 1)]);
        }
        __syncthreads();
        if (kc + 2 < 4) { load_stage(kc + 2); CP_COMMIT(); }
    }

#pragma unroll
    for (int mt = 0; mt < 4; mt++) {
        const int mloc = wm * 64 + mt * 16 + (lane >> 2);
#pragma unroll
        for (int nt = 0; nt < 8; nt++) {
            const int nl = n0 + wn * 64 + nt * 8 + (lane & 3) * 2;
            float2 bb = *(const float2*)&bias[nl];
            *(uint32_t*)&g_edge_hi[(size_t)(m0 + mloc) * 1024 + nl] =
                packh(fmaxf(acc[mt][nt][0] + bb.x, 0.f), fmaxf(acc[mt][nt][1] + bb.y, 0.f));
            *(uint32_t*)&g_edge_hi[(size_t)(m0 + mloc + 8) * 1024 + nl] =
                packh(fmaxf(acc[mt][nt][2] + bb.x, 0.f), fmaxf(acc[mt][nt][3] + bb.y, 0.f));
        }
    }
}

// ===========================================================================
// UV GEMM: U = head_rep @ Wcat_top, V = tail_rep @ Wcat_bot (+bcat folded)
// ===========================================================================
__global__ __launch_bounds__(256, 1) void k_uv(const float* __restrict__ bcat)
{
    extern __shared__ __align__(1024) char smc[];
    const uint32_t sb = smem_u32(smc);
    const int t = threadIdx.x;
    const int lane = t & 31, wid = t >> 5;
    const int wm = wid >> 2, wn = wid & 3;
    const int m0 = blockIdx.x * 128, n0 = blockIdx.y * 256;
    const int zsel = blockIdx.z;
    const int koff = zsel * 512;
    __half* dst = zsel ? g_V : g_U;

    auto load_stage = [&](int kc) {
        const uint32_t base = sb + (kc & 1) * UVSTAGE;
#pragma unroll
        for (int i = 0; i < 8; i++) {
            int idx = t + i * 256;
            int row = idx >> 4, j = idx & 15;
            uint32_t d = (uint32_t)row * 256 + (((uint32_t)j * 16) ^ ((uint32_t)(row & 7) << 4));
            CP16(base + UV_A + d, &g_edge_hi[(size_t)(m0 + row) * 1024 + koff + kc * 128 + j * 8]);
        }
#pragma unroll
        for (int i = 0; i < 16; i++) {
            int idx = t + i * 256;
            int row = idx >> 4, j = idx & 15;
            uint32_t d = (uint32_t)row * 256 + (((uint32_t)j * 16) ^ ((uint32_t)(row & 7) << 4));
            CP16(base + UV_B + d, &g_wcatT[(size_t)(n0 + row) * 1024 + koff + kc * 128 + j * 8]);
        }
    };
    load_stage(0); CP_COMMIT();
    load_stage(1); CP_COMMIT();

    const uint32_t xorv = (lane & 7) << 4;
    const uint32_t khb  = (lane >> 4) * 16;
    const uint32_t arow = (uint32_t)(wm * 64 + (lane & 15)) * 256;
    const uint32_t brow = (uint32_t)(wn * 64 + (lane & 15)) * 256;

    float acc[4][8][4];
#pragma unroll
    for (int a = 0; a < 4; a++)
#pragma unroll
        for (int b = 0; b < 8; b++)
#pragma unroll
            for (int c = 0; c < 4; c++) acc[a][b][c] = 0.f;

    for (int kc = 0; kc < 4; kc++) {
        if (kc == 3) { WAITG(0); } else { WAITG(1); }
        __syncthreads();
        const uint32_t base = sb + (kc & 1) * UVSTAGE;
#pragma unroll
        for (int ks = 0; ks < 8; ks++) {
            const uint32_t col = (uint32_t)(ks * 32 + khb) ^ xorv;
            uint32_t bf[4][4];
#pragma unroll
            for (int q = 0; q < 4; q++)
                ldsm4(bf[q], base + UV_B + brow + q * 16 * 256 + col);
            uint32_t ah[4][4];
#pragma unroll
            for (int mt = 0; mt < 4; mt++)
                ldsm4(ah[mt], base + UV_A + arow + mt * 16 * 256 + col);
#pragma unroll
            for (int mt = 0; mt < 4; mt++)
#pragma unroll
                for (int nt = 0; nt < 8; nt++)
                    mma16816(acc[mt][nt], ah[mt],
                             bf[nt >> 1][nt & 1], bf[nt >> 1][2 + (nt & 1)]);
        }
        __syncthreads();
        if (kc + 2 < 4) { load_stage(kc + 2); CP_COMMIT(); }
    }

    const float zf = zsel ? 1.f : 0.f;   // fold bcat into V only
#pragma unroll
    for (int mt = 0; mt < 4; mt++) {
        const int mloc = wm * 64 + mt * 16 + (lane >> 2);
#pragma unroll
        for (int nt = 0; nt < 8; nt++) {
            const int nl = wn * 64 + nt * 8 + (lane & 3) * 2;
            float2 bb = *(const float2*)&bcat[n0 + nl];
            float bx = bb.x * zf, by = bb.y * zf;
            *(uint32_t*)&dst[(size_t)(m0 + mloc) * POOL + n0 + nl] =
                packh(acc[mt][nt][0] + bx, acc[mt][nt][1] + by);
            *(uint32_t*)&dst[(size_t)(m0 + mloc + 8) * POOL + n0 + nl] =
                packh(acc[mt][nt][2] + bx, acc[mt][nt][3] + by);
        }
    }
}

// ===========================================================================
// z-pass (R12 structure): z = (U[p0] + V'[p1]) * union -> GEMM3 -> +freq
// 256 threads, 2 CTAs/SM. 32 chunks of 128 pool cols.
// ===========================================================================
__global__ __launch_bounds__(256, 2) void k_zpass(
    const float* __restrict__ unionf,
    const int*   __restrict__ pairs,
    const int*   __restrict__ obj_preds,
    const float* __restrict__ bctx,
    const float* __restrict__ freq,
    float*       __restrict__ out)
{
    extern __shared__ __align__(1024) char smc[];
    const uint32_t sb = smem_u32(smc);
    const int t = threadIdx.x;
    const int lane = t & 31, wid = t >> 5;
    const int gm = wid >> 1, gn = wid & 1;
    const int r0 = blockIdx.x * 128;

    int* p0s = (int*)(smc + ZP_P0);
    int* p1s = (int*)(smc + ZP_P1);
    int* opx = (int*)(smc + ZP_OP);

    if (t < 128) {
        int a = pairs[(size_t)(r0 + t) * 2 + 0];
        int b = pairs[(size_t)(r0 + t) * 2 + 1];
        p0s[t] = a; p1s[t] = b;
        opx[t] = obj_preds[a] * NOBJCLS + obj_preds[b];
    }
    __syncthreads();

    const int m = t >> 1;
    const int coff = (t & 1) * 64;
    const int sub = t & 1;
    const uint32_t xorm = (uint32_t)(m & 7) << 4;
    const __half* Ubase = &g_U[(size_t)p0s[m] * POOL];
    const __half* Vbase = &g_V[(size_t)p1s[m] * POOL];
    const float*  ubase = &unionf[(size_t)(r0 + m) * POOL];

    const uint32_t xorv = (lane & 7) << 4;
    const uint32_t khb  = (lane >> 4) * 16;
    const uint32_t zrow = (uint32_t)(gm * 32 + (lane & 15)) * 128;
    const uint32_t wrow = (uint32_t)(gn * 32 + (lane & 15)) * 128;

    float acc3[2][4][4];
#pragma unroll
    for (int a = 0; a < 2; a++)
#pragma unroll
        for (int b = 0; b < 4; b++)
#pragma unroll
            for (int c = 0; c < 4; c++) acc3[a][b][c] = 0.f;

    for (int nc = 0; nc < 32; nc++) {
        const int n0 = nc * 128;

        // W_ctx tiles: 2 subs of [64cls][64k] via cp.async
#pragma unroll
        for (int i = 0; i < 4; i++) {
            int idx = t + i * 256;
            int s = idx >> 9, rem = idx & 511, row = rem >> 3, j = rem & 7;
            uint32_t d = (uint32_t)(ZP_WC + s * 8192) + (uint32_t)row * 128 +
                         (((uint32_t)j * 16) ^ ((uint32_t)(row & 7) << 4));
            CP16(sb + d, &g_wctxT[(size_t)row * POOL + n0 + s * 64 + j * 8]);
        }
        CP_COMMIT();

        // elementwise: 64 cols per thread (bcat pre-folded into V)
        {
            const uint4*  Up = (const uint4*)(Ubase + n0 + coff);
            const uint4*  Vp = (const uint4*)(Vbase + n0 + coff);
            const float4* up = (const float4*)(ubase + n0 + coff);
#pragma unroll
            for (int j = 0; j < 8; j++) {
                uint4 Uv = Up[j], Vv = Vp[j];
                float4 u0 = up[2 * j], u1 = up[2 * j + 1];
                const __half2* pu = (const __half2*)&Uv;
                const __half2* pv = (const __half2*)&Vv;
                float2 f0 = __half22float2(pu[0]), g0 = __half22float2(pv[0]);
                float2 f1 = __half22float2(pu[1]), g1 = __half22float2(pv[1]);
                float2 f2 = __half22float2(pu[2]), g2 = __half22float2(pv[2]);
                float2 f3 = __half22float2(pu[3]), g3 = __half22float2(pv[3]);
                uint4 o;
                o.x = packh((f0.x + g0.x) * u0.x, (f0.y + g0.y) * u0.y);
                o.y = packh((f1.x + g1.x) * u0.z, (f1.y + g1.y) * u0.w);
                o.z = packh((f2.x + g2.x) * u1.x, (f2.y + g2.y) * u1.y);
                o.w = packh((f3.x + g3.x) * u1.z, (f3.y + g3.y) * u1.w);
                *(uint4*)(smc + ZP_Z + sub * 16384 + (uint32_t)m * 128 +
                          (((uint32_t)j * 16) ^ xorm)) = o;
            }
        }
        WAITG(0);
        __syncthreads();

        // GEMM3: acc3 += z[128][128k] x Wctx[64cls][128k]
#pragma unroll
        for (int s = 0; s < 2; s++) {
#pragma unroll
            for (int ks = 0; ks < 4; ks++) {
                const uint32_t col = (uint32_t)(ks * 32 + khb) ^ xorv;
                uint32_t bf[2][4];
                ldsm4(bf[0], sb + ZP_WC + s * 8192 + wrow + col);
                ldsm4(bf[1], sb + ZP_WC + s * 8192 + wrow + 16 * 128 + col);
                uint32_t zfr[2][4];
#pragma unroll
                for (int mt = 0; mt < 2; mt++)
                    ldsm4(zfr[mt], sb + ZP_Z + s * 16384 + zrow + mt * 16 * 128 + col);
#pragma unroll
                for (int mt = 0; mt < 2; mt++)
#pragma unroll
                    for (int nt = 0; nt < 4; nt++)
                        mma16816(acc3[mt][nt], zfr[mt],
                                 bf[nt >> 1][nt & 1], bf[nt >> 1][2 + (nt & 1)]);
            }
        }
        __syncthreads();
    }

    // ---------------- final: out = acc3 + bctx + freq ----------------
#pragma unroll
    for (int mt = 0; mt < 2; mt++) {
        const int m0l = gm * 32 + mt * 16 + (lane >> 2);
#pragma unroll
        for (int r = 0; r < 2; r++) {
            const int mm = m0l + r * 8;
            const int pidx = opx[mm];
            const float* fr = &freq[(size_t)pidx * NRELCLS];
            float* op = &out[(size_t)(r0 + mm) * NRELCLS];
#pragma unroll
            for (int nt = 0; nt < 4; nt++) {
                const int c = gn * 32 + nt * 8 + (lane & 3) * 2;
                if (c < NRELCLS)
                    op[c] = acc3[mt][nt][r * 2 + 0] + bctx[c] + fr[c];
                if (c + 1 < NRELCLS)
                    op[c + 1] = acc3[mt][nt][r * 2 + 1] + bctx[c + 1] + fr[c + 1];
            }
        }
    }
}

// ===========================================================================
extern "C" void kernel_launch(void* const* d_in, const int* in_sizes, int n_in,
                              void* d_out, int out_size)
{
    const float* edge_ctx   = (const float*)d_in[0];
    const float* unionf     = (const float*)d_in[1];
    const int*   pairs      = (const int*)  d_in[2];
    const int*   obj_preds  = (const int*)  d_in[3];
    const float* W_post_emb = (const float*)d_in[4];
    const float* b_post_emb = (const float*)d_in[5];
    const float* W_post_cat = (const float*)d_in[6];
    const float* b_post_cat = (const float*)d_in[7];
    const float* W_ctx      = (const float*)d_in[8];
    const float* b_ctx      = (const float*)d_in[9];
    const float* freq       = (const float*)d_in[10];
    float* out = (float*)d_out;

    cudaFuncSetAttribute(k_gemm1_mma, cudaFuncAttributeMaxDynamicSharedMemorySize, SMEM_UV);
    cudaFuncSetAttribute(k_uv,        cudaFuncAttributeMaxDynamicSharedMemorySize, SMEM_UV);
    cudaFuncSetAttribute(k_zpass,     cudaFuncAttributeMaxDynamicSharedMemorySize, SMEM_ZP);

    k_ec_prep<<<(NOBJ * HID) / 256, 256>>>(edge_ctx);
    k_wemb_prep<<<dim3(1024 / 32, HID / 32), dim3(32, 8)>>>(W_post_emb);
    k_wcat_prep<<<dim3(POOL / 32, 1024 / 32), dim3(32, 8)>>>(W_post_cat);
    k_wctx_prep<<<(64 * POOL) / 256, 256>>>(W_ctx);
    k_gemm1_mma<<<dim3(NOBJ / 128, 1024 / 256), 256, SMEM_UV>>>(b_post_emb);
    k_uv<<<dim3(NOBJ / 128, POOL / 256, 2), 256, SMEM_UV>>>(b_post_cat);
    k_zpass<<<NREL / 128, 256, SMEM_ZP>>>(unionf, pairs, obj_preds,
                                          b_ctx, freq, out);
}

// round 15
// speedup vs baseline: 1.4469x; 1.0833x over previous
#include <cuda_runtime.h>
#include <cuda_fp16.h>
#include <cstdint>

#define HID      512
#define NOBJ     8192
#define NREL     32768
#define POOL     4096
#define NRELCLS  51
#define NOBJCLS  151

// -------------------- device scratch --------------------
__device__ __align__(256) __half g_edge_hi[NOBJ * 1024];
__device__ __align__(256) __half g_wcatT[POOL * 1024];   // [n][k] fp16
__device__ __align__(256) __half g_wctxT[64 * POOL];     // [cls pad64][k] fp16
__device__ __align__(256) __half g_ec_hi[NOBJ * HID];    // edge_ctx fp16
__device__ __align__(256) __half g_wembT[1024 * HID];    // [n][k] fp16
__device__ __align__(256) __half g_U[NOBJ * POOL];       // head_rep @ Wcat_top
__device__ __align__(256) __half g_V[NOBJ * POOL];       // tail_rep @ Wcat_bot + bcat

// -------------------- helpers --------------------
__device__ __forceinline__ uint32_t smem_u32(const void* p) {
    uint32_t a;
    asm("{ .reg .u64 t; cvta.to.shared.u64 t, %1; cvt.u32.u64 %0, t; }" : "=r"(a) : "l"(p));
    return a;
}
#define CP16(d, s)   asm volatile("cp.async.cg.shared.global [%0], [%1], 16;" :: "r"(d), "l"(s) : "memory")
#define CP_COMMIT()  asm volatile("cp.async.commit_group;" ::: "memory")
#define WAITG(n)     asm volatile("cp.async.wait_group %0;" :: "n"(n) : "memory")

__device__ __forceinline__ void ldsm4(uint32_t* r, uint32_t a) {
    asm volatile("ldmatrix.sync.aligned.m8n8.x4.shared.b16 {%0,%1,%2,%3}, [%4];"
                 : "=r"(r[0]), "=r"(r[1]), "=r"(r[2]), "=r"(r[3]) : "r"(a));
}
__device__ __forceinline__ void mma16816(float* d, const uint32_t* a, uint32_t b0, uint32_t b1) {
    asm volatile(
        "mma.sync.aligned.m16n8k16.row.col.f32.f16.f16.f32 "
        "{%0,%1,%2,%3}, {%4,%5,%6,%7}, {%8,%9}, {%0,%1,%2,%3};"
        : "+f"(d[0]), "+f"(d[1]), "+f"(d[2]), "+f"(d[3])
        : "r"(a[0]), "r"(a[1]), "r"(a[2]), "r"(a[3]), "r"(b0), "r"(b1));
}
__device__ __forceinline__ uint32_t packh(float e0, float e1) {
    uint32_t r;
    asm("cvt.rn.f16x2.f32 %0, %1, %2;" : "=r"(r) : "f"(e1), "f"(e0));  // low = e0
    return r;
}

// -------------------- smem layouts --------------------
#define GSTAGE   32768           // A [128m][64k] 16KB + B [128n][64k] 16KB
#define G_A      0
#define G_B      16384
#define SMEM_G   65536           // 64KB -> 2 CTAs/SM

#define ZP_Z     0               // 2 subs of z [128m][64k] fp16 = 32KB
#define ZP_WC    32768           // 2 subs of Wctx [64cls][64k] = 16KB
#define ZP_P0    49152
#define ZP_P1    49664
#define ZP_OP    50176
#define SMEM_ZP  50688

// ===========================================================================
// Preps
// ===========================================================================
__global__ void k_ec_prep(const float* __restrict__ src) {
    int idx = blockIdx.x * 256 + threadIdx.x;
    g_ec_hi[idx] = __float2half_rn(src[idx]);
}

__global__ void k_wemb_prep(const float* __restrict__ src) {  // [512][1024] -> [1024][512]
    __shared__ float tile[32][33];
    int tx = threadIdx.x, ty = threadIdx.y;
    int c0 = blockIdx.x * 32, r0 = blockIdx.y * 32;
    for (int i = ty; i < 32; i += 8)
        tile[i][tx] = src[(size_t)(r0 + i) * 1024 + c0 + tx];
    __syncthreads();
    for (int i = ty; i < 32; i += 8)
        g_wembT[(size_t)(c0 + i) * HID + r0 + tx] = __float2half_rn(tile[tx][i]);
}

__global__ void k_wcat_prep(const float* __restrict__ src) {  // [1024][4096] -> [4096][1024]
    __shared__ float tile[32][33];
    int tx = threadIdx.x, ty = threadIdx.y;
    int c0 = blockIdx.x * 32, r0 = blockIdx.y * 32;
    for (int i = ty; i < 32; i += 8)
        tile[i][tx] = src[(size_t)(r0 + i) * POOL + c0 + tx];
    __syncthreads();
    for (int i = ty; i < 32; i += 8)
        g_wcatT[(size_t)(c0 + i) * 1024 + r0 + tx] = __float2half_rn(tile[tx][i]);
}

__global__ void k_wctx_prep(const float* __restrict__ Wctx) {
    int idx = blockIdx.x * 256 + threadIdx.x;   // 64*4096
    int c = idx >> 12, k = idx & 4095;
    float v = (c < NRELCLS) ? Wctx[(size_t)k * NRELCLS + c] : 0.f;
    g_wctxT[idx] = __float2half_rn(v);
}

// ===========================================================================
// GEMM1 (2 CTAs/SM): edge_rep = relu(edge_ctx @ W_post_emb + b) -> fp16
// 256 threads, CTA tile M128 x N128, warp grid 4m x 2n (tile 32x64),
// K=512 in 8 stages of 64.
// ===========================================================================
__global__ __launch_bounds__(256, 2) void k_gemm1_mma(const float* __restrict__ bias)
{
    extern __shared__ __align__(1024) char smc[];
    const uint32_t sb = smem_u32(smc);
    const int t = threadIdx.x;
    const int lane = t & 31, wid = t >> 5;
    const int wm = wid >> 1, wn = wid & 1;
    const int m0 = blockIdx.x * 128, n0 = blockIdx.y * 128;

    auto load_stage = [&](int kc) {
        const uint32_t base = sb + (kc & 1) * GSTAGE;
#pragma unroll
        for (int i = 0; i < 4; i++) {
            int idx = t + i * 256;
            int row = idx >> 3, j = idx & 7;
            uint32_t d = (uint32_t)row * 128 + (((uint32_t)j * 16) ^ ((uint32_t)(row & 7) << 4));
            CP16(base + G_A + d, &g_ec_hi[(size_t)(m0 + row) * HID + kc * 64 + j * 8]);
            CP16(base + G_B + d, &g_wembT[(size_t)(n0 + row) * HID + kc * 64 + j * 8]);
        }
    };
    load_stage(0); CP_COMMIT();
    load_stage(1); CP_COMMIT();

    const uint32_t xorv = (lane & 7) << 4;
    const uint32_t khb  = (lane >> 4) * 16;
    const uint32_t arow = (uint32_t)(wm * 32 + (lane & 15)) * 128;
    const uint32_t brow = (uint32_t)(wn * 64 + (lane & 15)) * 128;

    float acc[2][8][4];
#pragma unroll
    for (int a = 0; a < 2; a++)
#pragma unroll
        for (int b = 0; b < 8; b++)
#pragma unroll
            for (int c = 0; c < 4; c++) acc[a][b][c] = 0.f;

    for (int kc = 0; kc < 8; kc++) {
        if (kc == 7) { WAITG(0); } else { WAITG(1); }
        __syncthreads();
        const uint32_t base = sb + (kc & 1) * GSTAGE;
#pragma unroll
        for (int ks = 0; ks < 4; ks++) {
            const uint32_t col = (uint32_t)(ks * 32 + khb) ^ xorv;
            uint32_t bf[4][4];
#pragma unroll
            for (int q = 0; q < 4; q++)
                ldsm4(bf[q], base + G_B + brow + q * 16 * 128 + col);
            uint32_t ah[2][4];
#pragma unroll
            for (int mt = 0; mt < 2; mt++)
                ldsm4(ah[mt], base + G_A + arow + mt * 16 * 128 + col);
#pragma unroll
            for (int mt = 0; mt < 2; mt++)
#pragma unroll
                for (int nt = 0; nt < 8; nt++)
                    mma16816(acc[mt][nt], ah[mt],
                             bf[nt >> 1][nt & 1], bf[nt >> 1][2 + (nt & 1)]);
        }
        __syncthreads();
        if (kc + 2 < 8) { load_stage(kc + 2); CP_COMMIT(); }
    }

#pragma unroll
    for (int mt = 0; mt < 2; mt++) {
        const int row = m0 + wm * 32 + mt * 16 + (lane >> 2);
#pragma unroll
        for (int nt = 0; nt < 8; nt++) {
            const int col = n0 + wn * 64 + nt * 8 + (lane & 3) * 2;
            float2 bb = *(const float2*)&bias[col];
            *(uint32_t*)&g_edge_hi[(size_t)row * 1024 + col] =
                packh(fmaxf(acc[mt][nt][0] + bb.x, 0.f), fmaxf(acc[mt][nt][1] + bb.y, 0.f));
            *(uint32_t*)&g_edge_hi[(size_t)(row + 8) * 1024 + col] =
                packh(fmaxf(acc[mt][nt][2] + bb.x, 0.f), fmaxf(acc[mt][nt][3] + bb.y, 0.f));
        }
    }
}

// ===========================================================================
// UV GEMM (2 CTAs/SM): U = head_rep @ Wcat_top, V = tail_rep @ Wcat_bot (+bcat)
// blockIdx.z selects half. 256 threads, M128 x N128, warp 32x64, 8 k-stages.
// ===========================================================================
__global__ __launch_bounds__(256, 2) void k_uv(const float* __restrict__ bcat)
{
    extern __shared__ __align__(1024) char smc[];
    const uint32_t sb = smem_u32(smc);
    const int t = threadIdx.x;
    const int lane = t & 31, wid = t >> 5;
    const int wm = wid >> 1, wn = wid & 1;
    const int m0 = blockIdx.x * 128, n0 = blockIdx.y * 128;
    const int zsel = blockIdx.z;
    const int koff = zsel * 512;
    __half* dst = zsel ? g_V : g_U;

    auto load_stage = [&](int kc) {
        const uint32_t base = sb + (kc & 1) * GSTAGE;
#pragma unroll
        for (int i = 0; i < 4; i++) {
            int idx = t + i * 256;
            int row = idx >> 3, j = idx & 7;
            uint32_t d = (uint32_t)row * 128 + (((uint32_t)j * 16) ^ ((uint32_t)(row & 7) << 4));
            CP16(base + G_A + d, &g_edge_hi[(size_t)(m0 + row) * 1024 + koff + kc * 64 + j * 8]);
            CP16(base + G_B + d, &g_wcatT[(size_t)(n0 + row) * 1024 + koff + kc * 64 + j * 8]);
        }
    };
    load_stage(0); CP_COMMIT();
    load_stage(1); CP_COMMIT();

    const uint32_t xorv = (lane & 7) << 4;
    const uint32_t khb  = (lane >> 4) * 16;
    const uint32_t arow = (uint32_t)(wm * 32 + (lane & 15)) * 128;
    const uint32_t brow = (uint32_t)(wn * 64 + (lane & 15)) * 128;

    float acc[2][8][4];
#pragma unroll
    for (int a = 0; a < 2; a++)
#pragma unroll
        for (int b = 0; b < 8; b++)
#pragma unroll
            for (int c = 0; c < 4; c++) acc[a][b][c] = 0.f;

    for (int kc = 0; kc < 8; kc++) {
        if (kc == 7) { WAITG(0); } else { WAITG(1); }
        __syncthreads();
        const uint32_t base = sb + (kc & 1) * GSTAGE;
#pragma unroll
        for (int ks = 0; ks < 4; ks++) {
            const uint32_t col = (uint32_t)(ks * 32 + khb) ^ xorv;
            uint32_t bf[4][4];
#pragma unroll
            for (int q = 0; q < 4; q++)
                ldsm4(bf[q], base + G_B + brow + q * 16 * 128 + col);
            uint32_t ah[2][4];
#pragma unroll
            for (int mt = 0; mt < 2; mt++)
                ldsm4(ah[mt], base + G_A + arow + mt * 16 * 128 + col);
#pragma unroll
            for (int mt = 0; mt < 2; mt++)
#pragma unroll
                for (int nt = 0; nt < 8; nt++)
                    mma16816(acc[mt][nt], ah[mt],
                             bf[nt >> 1][nt & 1], bf[nt >> 1][2 + (nt & 1)]);
        }
        __syncthreads();
        if (kc + 2 < 8) { load_stage(kc + 2); CP_COMMIT(); }
    }

    const float zf = zsel ? 1.f : 0.f;   // fold bcat into V only
#pragma unroll
    for (int mt = 0; mt < 2; mt++) {
        const int mloc = wm * 32 + mt * 16 + (lane >> 2);
#pragma unroll
        for (int nt = 0; nt < 8; nt++) {
            const int nl = n0 + wn * 64 + nt * 8 + (lane & 3) * 2;
            float2 bb = *(const float2*)&bcat[nl];
            float bx = bb.x * zf, by = bb.y * zf;
            *(uint32_t*)&dst[(size_t)(m0 + mloc) * POOL + nl] =
                packh(acc[mt][nt][0] + bx, acc[mt][nt][1] + by);
            *(uint32_t*)&dst[(size_t)(m0 + mloc + 8) * POOL + nl] =
                packh(acc[mt][nt][2] + bx, acc[mt][nt][3] + by);
        }
    }
}

// ===========================================================================
// z-pass (R12/R14 structure, unchanged): z = (U[p0]+V'[p1])*union -> GEMM3
// 256 threads, 2 CTAs/SM. 32 chunks of 128 pool cols.
// ===========================================================================
__global__ __launch_bounds__(256, 2) void k_zpass(
    const float* __restrict__ unionf,
    const int*   __restrict__ pairs,
    const int*   __restrict__ obj_preds,
    const float* __restrict__ bctx,
    const float* __restrict__ freq,
    float*       __restrict__ out)
{
    extern __shared__ __align__(1024) char smc[];
    const uint32_t sb = smem_u32(smc);
    const int t = threadIdx.x;
    const int lane = t & 31, wid = t >> 5;
    const int gm = wid >> 1, gn = wid & 1;
    const int r0 = blockIdx.x * 128;

    int* p0s = (int*)(smc + ZP_P0);
    int* p1s = (int*)(smc + ZP_P1);
    int* opx = (int*)(smc + ZP_OP);

    if (t < 128) {
        int a = pairs[(size_t)(r0 + t) * 2 + 0];
        int b = pairs[(size_t)(r0 + t) * 2 + 1];
        p0s[t] = a; p1s[t] = b;
        opx[t] = obj_preds[a] * NOBJCLS + obj_preds[b];
    }
    __syncthreads();

    const int m = t >> 1;
    const int coff = (t & 1) * 64;
    const int sub = t & 1;
    const uint32_t xorm = (uint32_t)(m & 7) << 4;
    const __half* Ubase = &g_U[(size_t)p0s[m] * POOL];
    const __half* Vbase = &g_V[(size_t)p1s[m] * POOL];
    const float*  ubase = &unionf[(size_t)(r0 + m) * POOL];

    const uint32_t xorv = (lane & 7) << 4;
    const uint32_t khb  = (lane >> 4) * 16;
    const uint32_t zrow = (uint32_t)(gm * 32 + (lane & 15)) * 128;
    const uint32_t wrow = (uint32_t)(gn * 32 + (lane & 15)) * 128;

    float acc3[2][4][4];
#pragma unroll
    for (int a = 0; a < 2; a++)
#pragma unroll
        for (int b = 0; b < 4; b++)
#pragma unroll
            for (int c = 0; c < 4; c++) acc3[a][b][c] = 0.f;

    for (int nc = 0; nc < 32; nc++) {
        const int n0 = nc * 128;

        // W_ctx tiles: 2 subs of [64cls][64k] via cp.async
#pragma unroll
        for (int i = 0; i < 4; i++) {
            int idx = t + i * 256;
            int s = idx >> 9, rem = idx & 511, row = rem >> 3, j = rem & 7;
            uint32_t d = (uint32_t)(ZP_WC + s * 8192) + (uint32_t)row * 128 +
                         (((uint32_t)j * 16) ^ ((uint32_t)(row & 7) << 4));
            CP16(sb + d, &g_wctxT[(size_t)row * POOL + n0 + s * 64 + j * 8]);
        }
        CP_COMMIT();

        // elementwise: 64 cols per thread (bcat pre-folded into V)
        {
            const uint4*  Up = (const uint4*)(Ubase + n0 + coff);
            const uint4*  Vp = (const uint4*)(Vbase + n0 + coff);
            const float4* up = (const float4*)(ubase + n0 + coff);
#pragma unroll
            for (int j = 0; j < 8; j++) {
                uint4 Uv = Up[j], Vv = Vp[j];
                float4 u0 = up[2 * j], u1 = up[2 * j + 1];
                const __half2* pu = (const __half2*)&Uv;
                const __half2* pv = (const __half2*)&Vv;
                float2 f0 = __half22float2(pu[0]), g0 = __half22float2(pv[0]);
                float2 f1 = __half22float2(pu[1]), g1 = __half22float2(pv[1]);
                float2 f2 = __half22float2(pu[2]), g2 = __half22float2(pv[2]);
                float2 f3 = __half22float2(pu[3]), g3 = __half22float2(pv[3]);
                uint4 o;
                o.x = packh((f0.x + g0.x) * u0.x, (f0.y + g0.y) * u0.y);
                o.y = packh((f1.x + g1.x) * u0.z, (f1.y + g1.y) * u0.w);
                o.z = packh((f2.x + g2.x) * u1.x, (f2.y + g2.y) * u1.y);
                o.w = packh((f3.x + g3.x) * u1.z, (f3.y + g3.y) * u1.w);
                *(uint4*)(smc + ZP_Z + sub * 16384 + (uint32_t)m * 128 +
                          (((uint32_t)j * 16) ^ xorm)) = o;
            }
        }
        WAITG(0);
        __syncthreads();

        // GEMM3: acc3 += z[128][128k] x Wctx[64cls][128k]
#pragma unroll
        for (int s = 0; s < 2; s++) {
#pragma unroll
            for (int ks = 0; ks < 4; ks++) {
                const uint32_t col = (uint32_t)(ks * 32 + khb) ^ xorv;
                uint32_t bf[2][4];
                ldsm4(bf[0], sb + ZP_WC + s * 8192 + wrow + col);
                ldsm4(bf[1], sb + ZP_WC + s * 8192 + wrow + 16 * 128 + col);
                uint32_t zfr[2][4];
#pragma unroll
                for (int mt = 0; mt < 2; mt++)
                    ldsm4(zfr[mt], sb + ZP_Z + s * 16384 + zrow + mt * 16 * 128 + col);
#pragma unroll
                for (int mt = 0; mt < 2; mt++)
#pragma unroll
                    for (int nt = 0; nt < 4; nt++)
                        mma16816(acc3[mt][nt], zfr[mt],
                                 bf[nt >> 1][nt & 1], bf[nt >> 1][2 + (nt & 1)]);
            }
        }
        __syncthreads();
    }

    // ---------------- final: out = acc3 + bctx + freq ----------------
#pragma unroll
    for (int mt = 0; mt < 2; mt++) {
        const int m0l = gm * 32 + mt * 16 + (lane >> 2);
#pragma unroll
        for (int r = 0; r < 2; r++) {
            const int mm = m0l + r * 8;
            const int pidx = opx[mm];
            const float* fr = &freq[(size_t)pidx * NRELCLS];
            float* op = &out[(size_t)(r0 + mm) * NRELCLS];
#pragma unroll
            for (int nt = 0; nt < 4; nt++) {
                const int c = gn * 32 + nt * 8 + (lane & 3) * 2;
                if (c < NRELCLS)
                    op[c] = acc3[mt][nt][r * 2 + 0] + bctx[c] + fr[c];
                if (c + 1 < NRELCLS)
                    op[c + 1] = acc3[mt][nt][r * 2 + 1] + bctx[c + 1] + fr[c + 1];
            }
        }
    }
}

// ===========================================================================
extern "C" void kernel_launch(void* const* d_in, const int* in_sizes, int n_in,
                              void* d_out, int out_size)
{
    const float* edge_ctx   = (const float*)d_in[0];
    const float* unionf     = (const float*)d_in[1];
    const int*   pairs      = (const int*)  d_in[2];
    const int*   obj_preds  = (const int*)  d_in[3];
    const float* W_post_emb = (const float*)d_in[4];
    const float* b_post_emb = (const float*)d_in[5];
    const float* W_post_cat = (const float*)d_in[6];
    const float* b_post_cat = (const float*)d_in[7];
    const float* W_ctx      = (const float*)d_in[8];
    const float* b_ctx      = (const float*)d_in[9];
    const float* freq       = (const float*)d_in[10];
    float* out = (float*)d_out;

    cudaFuncSetAttribute(k_gemm1_mma, cudaFuncAttributeMaxDynamicSharedMemorySize, SMEM_G);
    cudaFuncSetAttribute(k_uv,        cudaFuncAttributeMaxDynamicSharedMemorySize, SMEM_G);
    cudaFuncSetAttribute(k_zpass,     cudaFuncAttributeMaxDynamicSharedMemorySize, SMEM_ZP);

    k_ec_prep<<<(NOBJ * HID) / 256, 256>>>(edge_ctx);
    k_wemb_prep<<<dim3(1024 / 32, HID / 32), dim3(32, 8)>>>(W_post_emb);
    k_wcat_prep<<<dim3(POOL / 32, 1024 / 32), dim3(32, 8)>>>(W_post_cat);
    k_wctx_prep<<<(64 * POOL) / 256, 256>>>(W_ctx);
    k_gemm1_mma<<<dim3(NOBJ / 128, 1024 / 128), 256, SMEM_G>>>(b_post_emb);
    k_uv<<<dim3(NOBJ / 128, POOL / 128, 2), 256, SMEM_G>>>(b_post_cat);
    k_zpass<<<NREL / 128, 256, SMEM_ZP>>>(unionf, pairs, obj_preds,
                                          b_ctx, freq, out);
}